// round 16
// baseline (speedup 1.0000x reference)
#include <cuda_runtime.h>
#include <cuda_bf16.h>

// Problem shape
#define TT 512
#define II 10
#define HH 32
#define EE 8                 // batch elements per block (= MMA N)
#define CH 32                // timesteps per x chunk
#define NCH (TT / CH)        // 16
#define XPAD 16              // padded feature dim (K for x part)
#define ESTR (CH * XPAD + 4) // x elem stride in floats (+4: bank-conflict skew)
#define GSTRE 132            // gates elem stride in floats (528B, 16B-aligned)

typedef unsigned uu;

__device__ __forceinline__ uu tf32r(float f) {
    uu u; asm("cvt.rna.tf32.f32 %0, %1;" : "=r"(u) : "f"(f)); return u;
}
__device__ __forceinline__ float tanha(float x) {
    float r; asm("tanh.approx.f32 %0, %1;" : "=f"(r) : "f"(x)); return r;
}
// tf32: D += A(16x8) * B(8x8)
__device__ __forceinline__ void mma8(float& d0, float& d1, float& d2, float& d3,
                                     uu a0, uu a1, uu a2, uu a3, uu b0, uu b1) {
    asm("mma.sync.aligned.m16n8k8.row.col.f32.tf32.tf32.f32 "
        "{%0,%1,%2,%3},{%4,%5,%6,%7},{%8,%9},{%0,%1,%2,%3};"
        : "+f"(d0), "+f"(d1), "+f"(d2), "+f"(d3)
        : "r"(a0), "r"(a1), "r"(a2), "r"(a3), "r"(b0), "r"(b1));
}
// bf16: D += A(16x16) * B(16x8)
__device__ __forceinline__ void mma16(float& d0, float& d1, float& d2, float& d3,
                                      uu a0, uu a1, uu a2, uu a3, uu b0, uu b1) {
    asm("mma.sync.aligned.m16n8k16.row.col.f32.bf16.bf16.f32 "
        "{%0,%1,%2,%3},{%4,%5,%6,%7},{%8,%9},{%0,%1,%2,%3};"
        : "+f"(d0), "+f"(d1), "+f"(d2), "+f"(d3)
        : "r"(a0), "r"(a1), "r"(a2), "r"(a3), "r"(b0), "r"(b1));
}
// split (a,b) into packed bf16x2 hi word + residual lo word (a in low half)
__device__ __forceinline__ void bfsp(float a, float b, uu& hi, uu& lo) {
    __nv_bfloat16 xa = __float2bfloat16_rn(a), xb = __float2bfloat16_rn(b);
    hi = (uu)__bfloat16_as_ushort(xa) | ((uu)__bfloat16_as_ushort(xb) << 16);
    float ra = a - __bfloat162float(xa), rb = b - __bfloat162float(xb);
    lo = (uu)__bfloat16_as_ushort(__float2bfloat16_rn(ra))
       | ((uu)__bfloat16_as_ushort(__float2bfloat16_rn(rb)) << 16);
}
__device__ __forceinline__ unsigned sm32(const void* p) {
    return (unsigned)__cvta_generic_to_shared(p);
}
__device__ __forceinline__ void cp8(unsigned d, const void* s) {
    asm volatile("cp.async.ca.shared.global [%0], [%1], 8;" :: "r"(d), "l"(s));
}

// 128 threads, 8 elements/block, 4 blocks/SM (single wave for 512 CTAs).
// Warp w computes gate w for all 8 elements (W_hh bf16 hi/lo k16; x tf32 k8).
// ONE barrier per step: every warp redundantly computes the c/h update for the
// 8 states its own B-fragments need, so new h lands in registers already in
// fragment layout (no h SMEM exchange, no second barrier). Gates double-buffered.
__global__ void __launch_bounds__(128, 4) lstm_kernel(
    const float* __restrict__ x,     const float* __restrict__ h0,
    const float* __restrict__ c0,    const float* __restrict__ W_ih,
    const float* __restrict__ W_hh,  const float* __restrict__ b_ih,
    const float* __restrict__ b_hh,  const float* __restrict__ W_lin,
    const float* __restrict__ b_lin, float* __restrict__ out)
{
    __shared__ __align__(16) float x_sh[2][EE * ESTR];     // 33.0 KB
    __shared__ __align__(16) float g_sh[2][EE * GSTRE];    // 8.4 KB [buf][e*132+4k+g]

    const int tid  = threadIdx.x;
    const int w    = tid >> 5;          // warp = gate (0=i,1=f,2=g,3=o)
    const int lane = tid & 31;
    const int gid  = lane >> 2;         // MMA groupID (0..7) = element
    const int tig  = lane & 3;          // MMA thread-in-group
    const int base = blockIdx.x * EE;

    const float s     = (w == 2) ? 1.0f : 0.5f;   // sigmoid fold scale
    const float alpha = (w == 2) ? 1.0f : 0.5f;
    const float beta  = (w == 2) ? 0.0f : 0.5f;

    // ---- resident A fragments (same loaders as the 299us baseline) ----
    uu ahh[2][2][4], ahl[2][2][4];       // W_hh bf16 hi/lo, k16 layout
    uu ax[2][2][4];                      // W_ih tf32-hi, k8 layout
    float bv[2][2];
    #pragma unroll
    for (int mt = 0; mt < 2; mt++) {
        #pragma unroll
        for (int kt = 0; kt < 2; kt++) {
            #pragma unroll
            for (int rg = 0; rg < 4; rg++) {
                int row = 32 * w + 16 * mt + 8 * (rg & 1) + gid;
                int col = 16 * kt + 2 * tig + 8 * (rg >> 1);
                bfsp(W_hh[row * HH + col] * s, W_hh[row * HH + col + 1] * s,
                     ahh[mt][kt][rg], ahl[mt][kt][rg]);
            }
        }
        #pragma unroll
        for (int rg = 0; rg < 4; rg++) {
            int row = 32 * w + 16 * mt + 8 * (rg & 1) + gid;
            #pragma unroll
            for (int kc = 0; kc < 2; kc++) {
                int j = 8 * kc + 4 * (rg >> 1) + tig;
                ax[mt][kc][rg] = tf32r((j < II) ? W_ih[row * II + j] * s : 0.0f);
            }
        }
        int r0 = 32 * w + 16 * mt + gid;
        bv[mt][0] = (b_ih[r0]     + b_hh[r0])     * s;
        bv[mt][1] = (b_ih[r0 + 8] + b_hh[r0 + 8]) * s;
    }

    // ---- per-thread state: 8 states k = 8*(idx>>1) + 2*tig + (idx&1), elem gid ----
    float cst[8], hv[8];
    #pragma unroll
    for (int idx = 0; idx < 8; idx++) {
        int k = 8 * (idx >> 1) + 2 * tig + (idx & 1);
        cst[idx] = c0[(base + gid) * HH + k];
        hv[idx]  = h0[(base + gid) * HH + k];
    }
    // h B-fragments in registers: hhi[g2] packs (hv[2g2], hv[2g2+1])
    uu hhi[4], hlo[4];
    #pragma unroll
    for (int g2 = 0; g2 < 4; g2++) bfsp(hv[2 * g2], hv[2 * g2 + 1], hhi[g2], hlo[g2]);

    // ---- x prefetch ----
    #define PREFETCH(chunk, buf)                                                  \
        do {                                                                      \
            for (int p = tid; p < EE * CH * 5; p += 128) {                        \
                int pe = p / (CH * 5);                                            \
                int r2 = p - pe * (CH * 5);                                       \
                int t  = r2 / 5;                                                  \
                int pj = r2 - t * 5;                                              \
                const float* src = x + ((size_t)(base + pe) * TT +                \
                                        (chunk) * CH + t) * II + 2 * pj;          \
                cp8(sm32(&x_sh[buf][pe * ESTR + t * XPAD + 2 * pj]), src);        \
            }                                                                     \
            asm volatile("cp.async.commit_group;");                               \
        } while (0)

    PREFETCH(0, 0);
    // zero pad columns j=10..15 in both buffers
    for (int p = tid; p < 2 * EE * CH * 6; p += 128) {
        int bf = p / (EE * CH * 6);
        int r  = p - bf * (EE * CH * 6);
        int pe = r / (CH * 6);
        int r2 = r - pe * (CH * 6);
        int t  = r2 / 6;
        int jj = 10 + (r2 - t * 6);
        x_sh[bf][pe * ESTR + t * XPAD + jj] = 0.0f;
    }
    asm volatile("cp.async.wait_group 0;");
    __syncthreads();

    // ---- recurrence: ONE barrier per step ----
    for (int cix = 0; cix < NCH; cix++) {
        if (cix + 1 < NCH) { PREFETCH(cix + 1, (cix + 1) & 1); }
        const float* xc = x_sh[cix & 1] + gid * ESTR;

        for (int tt = 0; tt < CH; tt++) {
            // x fragments (tf32-hi)
            const float* xe = xc + tt * XPAD;
            uu bxh[4];
            #pragma unroll
            for (int kc = 0; kc < 2; kc++) {
                bxh[2 * kc]     = tf32r(xe[8 * kc + tig]);
                bxh[2 * kc + 1] = tf32r(xe[8 * kc + tig + 4]);
            }

            float* gw = g_sh[tt & 1];
            #pragma unroll
            for (int mt = 0; mt < 2; mt++) {
                float c10 = bv[mt][0], c11 = bv[mt][0];
                float c12 = bv[mt][1], c13 = bv[mt][1];
                float c20 = 0.f, c21 = 0.f, c22 = 0.f, c23 = 0.f;
                float c30 = 0.f, c31 = 0.f, c32 = 0.f, c33 = 0.f;

                #pragma unroll
                for (int kt = 0; kt < 2; kt++) {
                    mma16(c10, c11, c12, c13,
                          ahh[mt][kt][0], ahh[mt][kt][1], ahh[mt][kt][2], ahh[mt][kt][3],
                          hhi[2 * kt], hhi[2 * kt + 1]);
                    mma16(c20, c21, c22, c23,
                          ahh[mt][kt][0], ahh[mt][kt][1], ahh[mt][kt][2], ahh[mt][kt][3],
                          hlo[2 * kt], hlo[2 * kt + 1]);
                    mma16(c30, c31, c32, c33,
                          ahl[mt][kt][0], ahl[mt][kt][1], ahl[mt][kt][2], ahl[mt][kt][3],
                          hhi[2 * kt], hhi[2 * kt + 1]);
                }
                #pragma unroll
                for (int kc = 0; kc < 2; kc++) {
                    mma8(c10, c11, c12, c13,
                         ax[mt][kc][0], ax[mt][kc][1], ax[mt][kc][2], ax[mt][kc][3],
                         bxh[2 * kc], bxh[2 * kc + 1]);
                }

                float d0 = (c10 + c20) + c30;
                float d1 = (c11 + c21) + c31;
                float d2 = (c12 + c22) + c32;
                float d3 = (c13 + c23) + c33;
                float a0v = fmaf(alpha, tanha(d0), beta);
                float a1v = fmaf(alpha, tanha(d1), beta);
                float a2v = fmaf(alpha, tanha(d2), beta);
                float a3v = fmaf(alpha, tanha(d3), beta);
                // D value (row 16mt+gid(+8), col 2tig(+1)) -> gw[e*132 + 4k + w]
                int k0 = 16 * mt + gid;
                gw[(2 * tig)     * GSTRE + 4 * k0 + w]       = a0v;
                gw[(2 * tig + 1) * GSTRE + 4 * k0 + w]       = a1v;
                gw[(2 * tig)     * GSTRE + 4 * (k0 + 8) + w] = a2v;
                gw[(2 * tig + 1) * GSTRE + 4 * (k0 + 8) + w] = a3v;
            }
            __syncthreads();   // gates visible; double-buffer makes reuse WAR-safe

            // thread-local update of the 8 states this thread's fragments need
            const float4* gq = reinterpret_cast<const float4*>(
                g_sh[tt & 1] + gid * GSTRE);
            #pragma unroll
            for (int idx = 0; idx < 8; idx++) {
                int k = 8 * (idx >> 1) + 2 * tig + (idx & 1);
                float4 g4 = gq[k];                 // {i, f, g, o}
                cst[idx] = fmaf(g4.y, cst[idx], g4.x * g4.z);
                hv[idx]  = g4.w * tanha(cst[idx]);
            }
            #pragma unroll
            for (int g2 = 0; g2 < 4; g2++)
                bfsp(hv[2 * g2], hv[2 * g2 + 1], hhi[g2], hlo[g2]);
        }
        asm volatile("cp.async.wait_group 0;");
        __syncthreads();
    }

    // ---- final linear head (warp 0 holds full h per element) ----
    if (w == 0) {
        float v = 0.0f;
        #pragma unroll
        for (int idx = 0; idx < 8; idx++) {
            int k = 8 * (idx >> 1) + 2 * tig + (idx & 1);
            v = fmaf(hv[idx], W_lin[k], v);
        }
        v += __shfl_xor_sync(0xffffffffu, v, 1);
        v += __shfl_xor_sync(0xffffffffu, v, 2);
        if (tig == 0) out[base + gid] = v + b_lin[0];
    }
}

extern "C" void kernel_launch(void* const* d_in, const int* in_sizes, int n_in,
                              void* d_out, int out_size) {
    const float* x     = (const float*)d_in[0];
    const float* h0    = (const float*)d_in[1];
    const float* c0    = (const float*)d_in[2];
    const float* W_ih  = (const float*)d_in[3];
    const float* W_hh  = (const float*)d_in[4];
    const float* b_ih  = (const float*)d_in[5];
    const float* b_hh  = (const float*)d_in[6];
    const float* W_lin = (const float*)d_in[7];
    const float* b_lin = (const float*)d_in[8];
    float* out = (float*)d_out;

    int B = in_sizes[1] / HH;   // 4096
    lstm_kernel<<<B / EE, 128>>>(x, h0, c0, W_ih, W_hh, b_ih, b_hh, W_lin, b_lin, out);
}

// round 17
// speedup vs baseline: 1.0517x; 1.0517x over previous
#include <cuda_runtime.h>
#include <cuda_bf16.h>

// Problem shape
#define TT 512
#define II 10
#define HH 32
#define EE 16                // elements per block: two phase-shifted groups of 8
#define CH 16                // timesteps per x chunk
#define NCH (TT / CH)        // 32
#define XPAD 16              // padded feature dim (K for x part)
#define ESTR (CH * XPAD + 4) // x elem stride in floats (+4: bank-conflict skew)

typedef unsigned uu;

__device__ __forceinline__ uu tf32r(float f) {
    uu u; asm("cvt.rna.tf32.f32 %0, %1;" : "=r"(u) : "f"(f)); return u;
}
__device__ __forceinline__ float tanha(float x) {
    float r; asm("tanh.approx.f32 %0, %1;" : "=f"(r) : "f"(x)); return r;
}
// tf32: D += A(16x8) * B(8x8)
__device__ __forceinline__ void mma8(float& d0, float& d1, float& d2, float& d3,
                                     uu a0, uu a1, uu a2, uu a3, uu b0, uu b1) {
    asm("mma.sync.aligned.m16n8k8.row.col.f32.tf32.tf32.f32 "
        "{%0,%1,%2,%3},{%4,%5,%6,%7},{%8,%9},{%0,%1,%2,%3};"
        : "+f"(d0), "+f"(d1), "+f"(d2), "+f"(d3)
        : "r"(a0), "r"(a1), "r"(a2), "r"(a3), "r"(b0), "r"(b1));
}
// bf16: D += A(16x16) * B(16x8)
__device__ __forceinline__ void mma16(float& d0, float& d1, float& d2, float& d3,
                                      uu a0, uu a1, uu a2, uu a3, uu b0, uu b1) {
    asm("mma.sync.aligned.m16n8k16.row.col.f32.bf16.bf16.f32 "
        "{%0,%1,%2,%3},{%4,%5,%6,%7},{%8,%9},{%0,%1,%2,%3};"
        : "+f"(d0), "+f"(d1), "+f"(d2), "+f"(d3)
        : "r"(a0), "r"(a1), "r"(a2), "r"(a3), "r"(b0), "r"(b1));
}
// split (a,b) into packed bf16x2 hi word + residual lo word (a in low half)
__device__ __forceinline__ void bfsp(float a, float b, uu& hi, uu& lo) {
    __nv_bfloat16 xa = __float2bfloat16_rn(a), xb = __float2bfloat16_rn(b);
    hi = (uu)__bfloat16_as_ushort(xa) | ((uu)__bfloat16_as_ushort(xb) << 16);
    float ra = a - __bfloat162float(xa), rb = b - __bfloat162float(xb);
    lo = (uu)__bfloat16_as_ushort(__float2bfloat16_rn(ra))
       | ((uu)__bfloat16_as_ushort(__float2bfloat16_rn(rb)) << 16);
}
__device__ __forceinline__ unsigned sm32(const void* p) {
    return (unsigned)__cvta_generic_to_shared(p);
}
__device__ __forceinline__ void cp8(unsigned d, const void* s) {
    asm volatile("cp.async.ca.shared.global [%0], [%1], 8;" :: "r"(d), "l"(s));
}

// 128 threads, 16 elements/block as TWO groups of 8, phase-shifted half a step.
// Warp w computes gate w; each barrier window = update(group Y) + MMA(group X),
// so every window mixes tensor chains with ALU/MUFU/LSU work and the barrier
// count per element-step is halved vs the two-barrier baseline.
__global__ void __launch_bounds__(128, 2) lstm_kernel(
    const float* __restrict__ x,     const float* __restrict__ h0,
    const float* __restrict__ c0,    const float* __restrict__ W_ih,
    const float* __restrict__ W_hh,  const float* __restrict__ b_ih,
    const float* __restrict__ b_hh,  const float* __restrict__ W_lin,
    const float* __restrict__ b_lin, float* __restrict__ out)
{
    __shared__ __align__(16) float x_sh[2][EE * ESTR];       // 33.3 KB
    __shared__ __align__(16) uint2 hfrag_sh[2][16][8];       // 2 KB  [group]
    __shared__ __align__(16) float gates_sh[2][4][HH][8];    // 8 KB  [group]

    const int tid  = threadIdx.x;
    const int w    = tid >> 5;          // warp = gate (0=i,1=f,2=g,3=o)
    const int lane = tid & 31;
    const int gid  = lane >> 2;         // MMA groupID (0..7) = element-in-group
    const int tig  = lane & 3;          // MMA thread-in-group
    const int base = blockIdx.x * EE;

    const float s     = (w == 2) ? 1.0f : 0.5f;
    const float alpha = (w == 2) ? 1.0f : 0.5f;
    const float beta  = (w == 2) ? 0.0f : 0.5f;

    // ---- resident A fragments (shared by both groups) ----
    uu ahh[2][2][4], ahl[2][2][4];       // W_hh bf16 hi/lo, k16 layout
    uu ax[2][2][4];                      // W_ih tf32-hi, k8 layout
    float bv[2][2];
    #pragma unroll
    for (int mt = 0; mt < 2; mt++) {
        #pragma unroll
        for (int kt = 0; kt < 2; kt++) {
            #pragma unroll
            for (int rg = 0; rg < 4; rg++) {
                int row = 32 * w + 16 * mt + 8 * (rg & 1) + gid;
                int col = 16 * kt + 2 * tig + 8 * (rg >> 1);
                bfsp(W_hh[row * HH + col] * s, W_hh[row * HH + col + 1] * s,
                     ahh[mt][kt][rg], ahl[mt][kt][rg]);
            }
        }
        #pragma unroll
        for (int rg = 0; rg < 4; rg++) {
            int row = 32 * w + 16 * mt + 8 * (rg & 1) + gid;
            #pragma unroll
            for (int kc = 0; kc < 2; kc++) {
                int j = 8 * kc + 4 * (rg >> 1) + tig;
                ax[mt][kc][rg] = tf32r((j < II) ? W_ih[row * II + j] * s : 0.0f);
            }
        }
        int r0 = 32 * w + 16 * mt + gid;
        bv[mt][0] = (b_ih[r0]     + b_hh[r0])     * s;
        bv[mt][1] = (b_ih[r0 + 8] + b_hh[r0 + 8]) * s;
    }

    // ---- per-thread state: groups g=0,1; states (l,e) and (l+16,e) each ----
    const int e = tid & 7;
    const int l = tid >> 3;             // 0..15
    float cs[2][2], hs[2][2];
    #pragma unroll
    for (int g = 0; g < 2; g++) {
        int eg = base + 8 * g + e;
        cs[g][0] = c0[eg * HH + l];      cs[g][1] = c0[eg * HH + l + 16];
        hs[g][0] = h0[eg * HH + l];      hs[g][1] = h0[eg * HH + l + 16];
    }
    const float wl0 = W_lin[l];
    const float wl1 = W_lin[l + 16];

    // halfword indices into hfrag_sh[g] for states k=l, k=l+16
    unsigned short* hb16 = reinterpret_cast<unsigned short*>(hfrag_sh);
    const int kpA  = l >> 1;
    const int half = l & 1;
    const int iA0  = (kpA * 8 + e) * 4 + half;          // group offset +512*g
    const int iB0  = ((kpA + 8) * 8 + e) * 4 + half;

    #pragma unroll
    for (int g = 0; g < 2; g++) {   // initial h fragments
        __nv_bfloat16 bh = __float2bfloat16_rn(hs[g][0]);
        hb16[g * 512 + iA0] = __bfloat16_as_ushort(bh);
        hb16[g * 512 + iA0 + 2] = __bfloat16_as_ushort(
            __float2bfloat16_rn(hs[g][0] - __bfloat162float(bh)));
        __nv_bfloat16 bh2 = __float2bfloat16_rn(hs[g][1]);
        hb16[g * 512 + iB0] = __bfloat16_as_ushort(bh2);
        hb16[g * 512 + iB0 + 2] = __bfloat16_as_ushort(
            __float2bfloat16_rn(hs[g][1] - __bfloat162float(bh2)));
    }

    // ---- x prefetch ----
    #define PREFETCH(chunk, buf)                                                  \
        do {                                                                      \
            for (int p = tid; p < EE * CH * 5; p += 128) {                        \
                int pe = p / (CH * 5);                                            \
                int r2 = p - pe * (CH * 5);                                       \
                int t  = r2 / 5;                                                  \
                int pj = r2 - t * 5;                                              \
                const float* src = x + ((size_t)(base + pe) * TT +                \
                                        (chunk) * CH + t) * II + 2 * pj;          \
                cp8(sm32(&x_sh[buf][pe * ESTR + t * XPAD + 2 * pj]), src);        \
            }                                                                     \
            asm volatile("cp.async.commit_group;");                               \
        } while (0)

    PREFETCH(0, 0);
    for (int p = tid; p < 2 * EE * CH * 6; p += 128) {   // zero pad j=10..15
        int bf = p / (EE * CH * 6);
        int r  = p - bf * (EE * CH * 6);
        int pe = r / (CH * 6);
        int r2 = r - pe * (CH * 6);
        int t  = r2 / 6;
        int jj = 10 + (r2 - t * 6);
        x_sh[bf][pe * ESTR + t * XPAD + jj] = 0.0f;
    }
    asm volatile("cp.async.wait_group 0;");
    __syncthreads();

    // MMA window for group g at x pointer xe (one timestep)
    #define MMA_WIN(g, xe_)                                                       \
        do {                                                                      \
            uint2 hu[4];                                                          \
            _Pragma("unroll")                                                     \
            for (int kt = 0; kt < 2; kt++) {                                      \
                hu[2 * kt]     = hfrag_sh[g][8 * kt + tig][gid];                  \
                hu[2 * kt + 1] = hfrag_sh[g][8 * kt + tig + 4][gid];              \
            }                                                                     \
            uu bxh[4];                                                            \
            _Pragma("unroll")                                                     \
            for (int kc = 0; kc < 2; kc++) {                                      \
                bxh[2 * kc]     = tf32r((xe_)[8 * kc + tig]);                     \
                bxh[2 * kc + 1] = tf32r((xe_)[8 * kc + tig + 4]);                 \
            }                                                                     \
            _Pragma("unroll")                                                     \
            for (int mt = 0; mt < 2; mt++) {                                      \
                float c10 = bv[mt][0], c11 = bv[mt][0];                           \
                float c12 = bv[mt][1], c13 = bv[mt][1];                           \
                float c20 = 0.f, c21 = 0.f, c22 = 0.f, c23 = 0.f;                 \
                float c30 = 0.f, c31 = 0.f, c32 = 0.f, c33 = 0.f;                 \
                _Pragma("unroll")                                                 \
                for (int kt = 0; kt < 2; kt++) {                                  \
                    mma16(c10, c11, c12, c13,                                     \
                          ahh[mt][kt][0], ahh[mt][kt][1], ahh[mt][kt][2],         \
                          ahh[mt][kt][3], hu[2 * kt].x, hu[2 * kt + 1].x);        \
                    mma16(c20, c21, c22, c23,                                     \
                          ahh[mt][kt][0], ahh[mt][kt][1], ahh[mt][kt][2],         \
                          ahh[mt][kt][3], hu[2 * kt].y, hu[2 * kt + 1].y);        \
                    mma16(c30, c31, c32, c33,                                     \
                          ahl[mt][kt][0], ahl[mt][kt][1], ahl[mt][kt][2],         \
                          ahl[mt][kt][3], hu[2 * kt].x, hu[2 * kt + 1].x);        \
                }                                                                 \
                _Pragma("unroll")                                                 \
                for (int kc = 0; kc < 2; kc++) {                                  \
                    mma8(c10, c11, c12, c13,                                      \
                         ax[mt][kc][0], ax[mt][kc][1], ax[mt][kc][2],             \
                         ax[mt][kc][3], bxh[2 * kc], bxh[2 * kc + 1]);            \
                }                                                                 \
                float d0 = (c10 + c20) + c30;                                     \
                float d1 = (c11 + c21) + c31;                                     \
                float d2 = (c12 + c22) + c32;                                     \
                float d3 = (c13 + c23) + c33;                                     \
                *reinterpret_cast<float2*>(&gates_sh[g][w][16 * mt + gid][2 * tig]) = \
                    make_float2(fmaf(alpha, tanha(d0), beta),                     \
                                fmaf(alpha, tanha(d1), beta));                    \
                *reinterpret_cast<float2*>(&gates_sh[g][w][16 * mt + 8 + gid][2 * tig]) = \
                    make_float2(fmaf(alpha, tanha(d2), beta),                     \
                                fmaf(alpha, tanha(d3), beta));                    \
            }                                                                     \
        } while (0)

    // update window for group g
    #define UPD_WIN(g)                                                            \
        do {                                                                      \
            float iv = gates_sh[g][0][l][e],      fv = gates_sh[g][1][l][e];      \
            float gv = gates_sh[g][2][l][e],      ov = gates_sh[g][3][l][e];      \
            cs[g][0] = fmaf(fv, cs[g][0], iv * gv);                               \
            hs[g][0] = ov * tanha(cs[g][0]);                                      \
            __nv_bfloat16 bh = __float2bfloat16_rn(hs[g][0]);                     \
            hb16[(g) * 512 + iA0] = __bfloat16_as_ushort(bh);                     \
            hb16[(g) * 512 + iA0 + 2] = __bfloat16_as_ushort(                     \
                __float2bfloat16_rn(hs[g][0] - __bfloat162float(bh)));            \
            float iv2 = gates_sh[g][0][l + 16][e], fv2 = gates_sh[g][1][l + 16][e]; \
            float gv2 = gates_sh[g][2][l + 16][e], ov2 = gates_sh[g][3][l + 16][e]; \
            cs[g][1] = fmaf(fv2, cs[g][1], iv2 * gv2);                            \
            hs[g][1] = ov2 * tanha(cs[g][1]);                                     \
            __nv_bfloat16 bh2 = __float2bfloat16_rn(hs[g][1]);                    \
            hb16[(g) * 512 + iB0] = __bfloat16_as_ushort(bh2);                    \
            hb16[(g) * 512 + iB0 + 2] = __bfloat16_as_ushort(                     \
                __float2bfloat16_rn(hs[g][1] - __bfloat162float(bh2)));           \
        } while (0)

    // ---- staggered recurrence ----
    for (int cix = 0; cix < NCH; cix++) {
        if (cix + 1 < NCH) { PREFETCH(cix + 1, (cix + 1) & 1); }
        const float* xg0 = x_sh[cix & 1] + gid * ESTR;
        const float* xg1 = x_sh[cix & 1] + (8 + gid) * ESTR;

        MMA_WIN(0, xg0);                 // leading half-window: gates(G0, tt=0)
        __syncthreads();

        for (int tt = 0; tt < CH; tt++) {
            UPD_WIN(0);
            MMA_WIN(1, xg1 + tt * XPAD);
            __syncthreads();

            UPD_WIN(1);
            if (tt + 1 < CH) { MMA_WIN(0, xg0 + (tt + 1) * XPAD); }
            __syncthreads();
        }
        asm volatile("cp.async.wait_group 0;");
        __syncthreads();
    }

    // ---- final linear head ----
    float* scratch = &gates_sh[0][0][0][0];      // reuse as [16][16]
    scratch[e * 16 + l]       = fmaf(hs[0][0], wl0, hs[0][1] * wl1);
    scratch[(8 + e) * 16 + l] = fmaf(hs[1][0], wl0, hs[1][1] * wl1);
    __syncthreads();
    if (tid < EE) {
        float sum = b_lin[0];
        #pragma unroll
        for (int q = 0; q < 16; q++) sum += scratch[tid * 16 + q];
        out[base + tid] = sum;
    }
}

extern "C" void kernel_launch(void* const* d_in, const int* in_sizes, int n_in,
                              void* d_out, int out_size) {
    const float* x     = (const float*)d_in[0];
    const float* h0    = (const float*)d_in[1];
    const float* c0    = (const float*)d_in[2];
    const float* W_ih  = (const float*)d_in[3];
    const float* W_hh  = (const float*)d_in[4];
    const float* b_ih  = (const float*)d_in[5];
    const float* b_hh  = (const float*)d_in[6];
    const float* W_lin = (const float*)d_in[7];
    const float* b_lin = (const float*)d_in[8];
    float* out = (float*)d_out;

    int B = in_sizes[1] / HH;   // 4096
    lstm_kernel<<<B / EE, 128>>>(x, h0, c0, W_ih, W_hh, b_ih, b_hh, W_lin, b_lin, out);
}